// round 6
// baseline (speedup 1.0000x reference)
#include <cuda_runtime.h>
#include <cuda_bf16.h>
#include <cstdint>
#include <math.h>

#define B_  2
#define T_  2048
#define C_  2048
#define H_  16
#define HD_ 128
#define C3_ 6144
#define M_  (B_*T_)

// ---------------- scratch (no allocations allowed) ----------------
__device__ float g_qkv[(size_t)B_ * T_ * C3_];   // [B,T,3C] (q,k un-roped; rope fused in attn)
__device__ float g_att[(size_t)B_ * T_ * C_];    // attention out in [B,T,C]
__device__ float g_cos[T_ * 64];
__device__ float g_sin[T_ * 64];

// ---------------- RoPE tables ----------------
__global__ void rope_tables_k() {
    int idx = blockIdx.x * blockDim.x + threadIdx.x;
    if (idx >= T_ * 64) return;
    int t = idx >> 6, p = idx & 63;
    double theta = exp(-log(10000.0) * exp2((double)p) / 128.0);
    double ang = (double)(t + 1) * theta;
    g_cos[idx] = (float)cos(ang);
    g_sin[idx] = (float)sin(ang);
}

// ================= mma.sync helpers =================
__device__ __forceinline__ uint32_t smem_u32(const void* p) {
    uint32_t a;
    asm("{ .reg .u64 t; cvta.to.shared.u64 t, %1; cvt.u32.u64 %0, t; }" : "=r"(a) : "l"(p));
    return a;
}
__device__ __forceinline__ void mma_bf16(float* c, const uint32_t* a, const uint32_t* b) {
    asm volatile(
        "mma.sync.aligned.m16n8k16.row.col.f32.bf16.bf16.f32 "
        "{%0,%1,%2,%3}, {%4,%5,%6,%7}, {%8,%9}, {%0,%1,%2,%3};"
        : "+f"(c[0]), "+f"(c[1]), "+f"(c[2]), "+f"(c[3])
        : "r"(a[0]), "r"(a[1]), "r"(a[2]), "r"(a[3]), "r"(b[0]), "r"(b[1]));
}
__device__ __forceinline__ void ldsm_x4(uint32_t* d, uint32_t addr) {
    asm volatile("ldmatrix.sync.aligned.m8n8.x4.shared.b16 {%0,%1,%2,%3}, [%4];"
                 : "=r"(d[0]), "=r"(d[1]), "=r"(d[2]), "=r"(d[3]) : "r"(addr));
}
__device__ __forceinline__ void ldsm_x4_t(uint32_t* d, uint32_t addr) {
    asm volatile("ldmatrix.sync.aligned.m8n8.x4.trans.shared.b16 {%0,%1,%2,%3}, [%4];"
                 : "=r"(d[0]), "=r"(d[1]), "=r"(d[2]), "=r"(d[3]) : "r"(addr));
}
__device__ __forceinline__ void ldsm_x2(uint32_t* d, uint32_t addr) {
    asm volatile("ldmatrix.sync.aligned.m8n8.x2.shared.b16 {%0,%1}, [%2];"
                 : "=r"(d[0]), "=r"(d[1]) : "r"(addr));
}
// hi = top-16-bit truncation of fp32 (exact in bf16, residual exact)
__device__ __forceinline__ uint32_t pack_hi(float x0, float x1) {
    uint32_t u0 = __float_as_uint(x0), u1 = __float_as_uint(x1);
    return (u0 >> 16) | (u1 & 0xFFFF0000u);
}
__device__ __forceinline__ uint32_t pack_lo(float x0, float x1) {
    float h0 = __uint_as_float(__float_as_uint(x0) & 0xFFFF0000u);
    float h1 = __uint_as_float(__float_as_uint(x1) & 0xFFFF0000u);
    __nv_bfloat162 v = __floats2bfloat162_rn(x0 - h0, x1 - h1);
    return *reinterpret_cast<uint32_t*>(&v);
}

// ================= bf16x3 HMMA GEMM (NT): C = A[M,K]*B[N,K]^T + bias =================
#define GBK 32
#define ROWH 40
#define TILE_H_BYTES (128 * ROWH * 2)
#define G_STAGE (4 * TILE_H_BYTES)
#define GEMM_SMEM (2 * G_STAGE)

__global__ void __launch_bounds__(256)
gemm_mma_k(const float* __restrict__ A, const float* __restrict__ Bm,
           const float* __restrict__ bias, float* __restrict__ Cm,
           int K, int ldc) {
    extern __shared__ char smem[];
    const uint32_t sb = smem_u32(smem);
    const int tid = threadIdx.x;
    const int wid = tid >> 5, lid = tid & 31;
    const int m0 = blockIdx.y * 128, n0 = blockIdx.x * 128;

    const int lr = tid >> 1;
    const int lc0 = (tid & 1) * 16;
    const float* Ap = A + (size_t)(m0 + lr) * K + lc0;
    const float* Bp = Bm + (size_t)(n0 + lr) * K + lc0;
    const uint32_t sts_off = (uint32_t)(lr * ROWH + lc0) * 2;

    const int wm = (wid >> 2) * 64, wn = (wid & 3) * 32;
    const int a_row = (lid & 7) + ((lid >> 3) & 1) * 8;
    const int a_kb  = ((lid >> 4) & 1) * 8;
    const int b_row = lid & 7;
    const int b_kb  = ((lid >> 3) & 1) * 8;

    float acc[4][4][4];
#pragma unroll
    for (int i = 0; i < 4; i++)
#pragma unroll
        for (int j = 0; j < 4; j++)
#pragma unroll
            for (int c = 0; c < 4; c++) acc[i][j][c] = 0.f;

    const int nch = K / GBK;
    float4 la[4], lb[4];

#pragma unroll
    for (int j = 0; j < 4; j++) { la[j] = *(const float4*)(Ap + j * 4); lb[j] = *(const float4*)(Bp + j * 4); }
#pragma unroll
    for (int j = 0; j < 4; j++) {
        uint32_t o = sts_off + j * 8;
        *(uint2*)(smem + 0 * TILE_H_BYTES + o) = make_uint2(pack_hi(la[j].x, la[j].y), pack_hi(la[j].z, la[j].w));
        *(uint2*)(smem + 1 * TILE_H_BYTES + o) = make_uint2(pack_lo(la[j].x, la[j].y), pack_lo(la[j].z, la[j].w));
        *(uint2*)(smem + 2 * TILE_H_BYTES + o) = make_uint2(pack_hi(lb[j].x, lb[j].y), pack_hi(lb[j].z, lb[j].w));
        *(uint2*)(smem + 3 * TILE_H_BYTES + o) = make_uint2(pack_lo(lb[j].x, lb[j].y), pack_lo(lb[j].z, lb[j].w));
    }

    for (int ch = 0; ch < nch; ch++) {
        __syncthreads();
        if (ch + 1 < nch) {
            const size_t ko = (size_t)(ch + 1) * GBK;
#pragma unroll
            for (int j = 0; j < 4; j++) { la[j] = *(const float4*)(Ap + ko + j * 4); lb[j] = *(const float4*)(Bp + ko + j * 4); }
        }
        const uint32_t st = sb + (uint32_t)(ch & 1) * G_STAGE;
#pragma unroll
        for (int ks = 0; ks < 2; ks++) {
            uint32_t ah[4][4], al[4][4], bh[4][2], bl[4][2];
#pragma unroll
            for (int mt = 0; mt < 4; mt++) {
                uint32_t ro = (uint32_t)((wm + mt * 16 + a_row) * ROWH + ks * 16 + a_kb) * 2;
                ldsm_x4(ah[mt], st + 0 * TILE_H_BYTES + ro);
                ldsm_x4(al[mt], st + 1 * TILE_H_BYTES + ro);
            }
#pragma unroll
            for (int nt = 0; nt < 4; nt++) {
                uint32_t ro = (uint32_t)((wn + nt * 8 + b_row) * ROWH + ks * 16 + b_kb) * 2;
                ldsm_x2(bh[nt], st + 2 * TILE_H_BYTES + ro);
                ldsm_x2(bl[nt], st + 3 * TILE_H_BYTES + ro);
            }
#pragma unroll
            for (int mt = 0; mt < 4; mt++)
#pragma unroll
                for (int nt = 0; nt < 4; nt++) {
                    mma_bf16(acc[mt][nt], ah[mt], bh[nt]);
                    mma_bf16(acc[mt][nt], ah[mt], bl[nt]);
                    mma_bf16(acc[mt][nt], al[mt], bh[nt]);
                }
        }
        if (ch + 1 < nch) {
            char* dst = smem + ((ch + 1) & 1) * G_STAGE;
#pragma unroll
            for (int j = 0; j < 4; j++) {
                uint32_t o = sts_off + j * 8;
                *(uint2*)(dst + 0 * TILE_H_BYTES + o) = make_uint2(pack_hi(la[j].x, la[j].y), pack_hi(la[j].z, la[j].w));
                *(uint2*)(dst + 1 * TILE_H_BYTES + o) = make_uint2(pack_lo(la[j].x, la[j].y), pack_lo(la[j].z, la[j].w));
                *(uint2*)(dst + 2 * TILE_H_BYTES + o) = make_uint2(pack_hi(lb[j].x, lb[j].y), pack_hi(lb[j].z, lb[j].w));
                *(uint2*)(dst + 3 * TILE_H_BYTES + o) = make_uint2(pack_lo(lb[j].x, lb[j].y), pack_lo(lb[j].z, lb[j].w));
            }
        }
    }

    const int cr = lid >> 2, cc = (lid & 3) * 2;
#pragma unroll
    for (int mt = 0; mt < 4; mt++) {
#pragma unroll
        for (int nt = 0; nt < 4; nt++) {
            int gr = m0 + wm + mt * 16 + cr;
            int gc = n0 + wn + nt * 8 + cc;
            float b0 = bias[gc], b1 = bias[gc + 1];
            float* p0 = Cm + (size_t)gr * ldc + gc;
            float* p1 = Cm + (size_t)(gr + 8) * ldc + gc;
            *(float2*)p0 = make_float2(acc[mt][nt][0] + b0, acc[mt][nt][1] + b1);
            *(float2*)p1 = make_float2(acc[mt][nt][2] + b0, acc[mt][nt][3] + b1);
        }
    }
}

// ================= HMMA flash attention (causal, fused RoPE, bf16x3, pipelined) =================
// BQ=128, BK=64, 8 warps; warp w owns q rows [w*16, w*16+16).
// smem (halfs, rows padded to 136): Qh,Ql [128x128]; double-buffered stages of Kh,Kl,Vh,Vl [64x128].
#define FROWH 136
#define FQH 0
#define FQL 17408
#define FST0 34816                 // first stage base (halfs)
#define FSTAGE 34816               // stage stride (halfs)
#define KH_L 0
#define KL_L 8704
#define VH_L 17408
#define VL_L 26112
#define FA2_SMEM ((FST0 + 2 * FSTAGE) * 2)   // 208896 bytes

// full (blocking) K/V tile load for the prologue
__device__ __forceinline__ void fa_load_kv(uint16_t* stg, int b, int h, int kt, int tid) {
    const int r = tid >> 2;
    const int t = kt * 64 + r;
    const float* kp = g_qkv + (size_t)(b * T_ + t) * C3_ + C_ + h * HD_;
    const float* cp = g_cos + t * 64;
    const float* sp = g_sin + t * 64;
    const uint32_t so = (uint32_t)(r * FROWH);
    const int c0 = (tid & 3) * 16;
#pragma unroll
    for (int j = 0; j < 4; j++) {
        int c = c0 + j * 4;
        float4 xa = *(const float4*)(kp + c);
        float4 xb = *(const float4*)(kp + c + 64);
        float4 cs = *(const float4*)(cp + c);
        float4 sn = *(const float4*)(sp + c);
        float4 ra, rb;
        ra.x = xa.x * cs.x - xb.x * sn.x;  rb.x = xb.x * cs.x + xa.x * sn.x;
        ra.y = xa.y * cs.y - xb.y * sn.y;  rb.y = xb.y * cs.y + xa.y * sn.y;
        ra.z = xa.z * cs.z - xb.z * sn.z;  rb.z = xb.z * cs.z + xa.z * sn.z;
        ra.w = xa.w * cs.w - xb.w * sn.w;  rb.w = xb.w * cs.w + xa.w * sn.w;
        *(uint2*)(stg + KH_L + so + c)      = make_uint2(pack_hi(ra.x, ra.y), pack_hi(ra.z, ra.w));
        *(uint2*)(stg + KL_L + so + c)      = make_uint2(pack_lo(ra.x, ra.y), pack_lo(ra.z, ra.w));
        *(uint2*)(stg + KH_L + so + c + 64) = make_uint2(pack_hi(rb.x, rb.y), pack_hi(rb.z, rb.w));
        *(uint2*)(stg + KL_L + so + c + 64) = make_uint2(pack_lo(rb.x, rb.y), pack_lo(rb.z, rb.w));
    }
    const float* vp = kp + C_;
    const int vc0 = (tid & 3) * 32;
#pragma unroll
    for (int j = 0; j < 8; j++) {
        int c = vc0 + j * 4;
        float4 v = *(const float4*)(vp + c);
        *(uint2*)(stg + VH_L + so + c) = make_uint2(pack_hi(v.x, v.y), pack_hi(v.z, v.w));
        *(uint2*)(stg + VL_L + so + c) = make_uint2(pack_lo(v.x, v.y), pack_lo(v.z, v.w));
    }
}

__global__ void __launch_bounds__(256, 1)
flash_attn_mma_k() {
    extern __shared__ uint16_t sh[];
    const uint32_t sb = smem_u32(sh);
    const int tid = threadIdx.x, wid = tid >> 5, lane = tid & 31;
    const int qb = (int)gridDim.x - 1 - (int)blockIdx.x;  // big work first (tail packing)
    const int h = blockIdx.y, b = blockIdx.z;
    const int q0 = qb * 128;
    const float scale = 0.08838834764831845f;  // 1/sqrt(128)

    // ---- Q tile load + RoPE + hi/lo split (2 threads per row)
    {
        const int r = tid >> 1, c0 = (tid & 1) * 32;
        const int t = q0 + r;
        const float* qp = g_qkv + (size_t)(b * T_ + t) * C3_ + h * HD_;
        const float* cp = g_cos + t * 64;
        const float* sp = g_sin + t * 64;
        const uint32_t so = (uint32_t)(r * FROWH);
#pragma unroll
        for (int j = 0; j < 8; j++) {
            int c = c0 + j * 4;
            float4 xa = *(const float4*)(qp + c);
            float4 xb = *(const float4*)(qp + c + 64);
            float4 cs = *(const float4*)(cp + c);
            float4 sn = *(const float4*)(sp + c);
            float4 ra, rb;
            ra.x = xa.x * cs.x - xb.x * sn.x;  rb.x = xb.x * cs.x + xa.x * sn.x;
            ra.y = xa.y * cs.y - xb.y * sn.y;  rb.y = xb.y * cs.y + xa.y * sn.y;
            ra.z = xa.z * cs.z - xb.z * sn.z;  rb.z = xb.z * cs.z + xa.z * sn.z;
            ra.w = xa.w * cs.w - xb.w * sn.w;  rb.w = xb.w * cs.w + xa.w * sn.w;
            *(uint2*)(sh + FQH + so + c)      = make_uint2(pack_hi(ra.x, ra.y), pack_hi(ra.z, ra.w));
            *(uint2*)(sh + FQL + so + c)      = make_uint2(pack_lo(ra.x, ra.y), pack_lo(ra.z, ra.w));
            *(uint2*)(sh + FQH + so + c + 64) = make_uint2(pack_hi(rb.x, rb.y), pack_hi(rb.z, rb.w));
            *(uint2*)(sh + FQL + so + c + 64) = make_uint2(pack_lo(rb.x, rb.y), pack_lo(rb.z, rb.w));
        }
    }

    // ---- prologue: K/V tile 0 into stage 0
    fa_load_kv(sh + FST0, b, h, 0, tid);
    __syncthreads();

    float m_[2] = {-1e30f, -1e30f}, l_[2] = {0.f, 0.f};
    float o_[16][4];
#pragma unroll
    for (int nt = 0; nt < 16; nt++)
#pragma unroll
        for (int c = 0; c < 4; c++) o_[nt][c] = 0.f;

    const int r_ld = tid >> 2;
    const int ck0 = (tid & 3) * 16;
    const int cv0 = (tid & 3) * 32;
    const uint32_t so_ld = (uint32_t)(r_ld * FROWH);

    const int ktmax = 2 * qb + 1;
    for (int kt = 0; kt <= ktmax; kt++) {
        const uint32_t stb = sb + (uint32_t)(FST0 + (kt & 1) * FSTAGE) * 2;
        uint16_t* nst = sh + FST0 + ((kt + 1) & 1) * FSTAGE;
        const bool pf = (kt < ktmax);
        const int tnext = (kt + 1) * 64 + r_ld;
        const float* kp_n = g_qkv + (size_t)(b * T_ + tnext) * C3_ + C_ + h * HD_;

        // ---- issue K(kt+1) + cos/sin loads (land during S-compute)
        float4 kxa[4], kxb[4], kcs[4], ksn[4];
        if (pf) {
            const float* cp = g_cos + tnext * 64;
            const float* sp = g_sin + tnext * 64;
#pragma unroll
            for (int j = 0; j < 4; j++) {
                int c = ck0 + j * 4;
                kxa[j] = *(const float4*)(kp_n + c);
                kxb[j] = *(const float4*)(kp_n + c + 64);
                kcs[j] = *(const float4*)(cp + c);
                ksn[j] = *(const float4*)(sp + c);
            }
        }

        // ---- S = Q K^T  (bf16x3), warp tile 16x64
        float s[8][4];
#pragma unroll
        for (int nt = 0; nt < 8; nt++)
#pragma unroll
            for (int c = 0; c < 4; c++) s[nt][c] = 0.f;

#pragma unroll
        for (int kk = 0; kk < 8; kk++) {
            uint32_t aqh[4], aql[4];
            const uint32_t ar = sb + (uint32_t)((wid * 16 + (lane & 15)) * FROWH + kk * 16 + (lane >> 4) * 8) * 2;
            ldsm_x4(aqh, ar + FQH * 2);
            ldsm_x4(aql, ar + FQL * 2);
#pragma unroll
            for (int np = 0; np < 4; np++) {
                uint32_t bh[4], bl[4];
                const uint32_t br = stb + (uint32_t)((np * 16 + (lane & 7) + ((lane >> 4) & 1) * 8) * FROWH +
                                                     kk * 16 + ((lane >> 3) & 1) * 8) * 2;
                ldsm_x4(bh, br + KH_L * 2);
                ldsm_x4(bl, br + KL_L * 2);
                mma_bf16(s[2 * np],     aqh, bh);
                mma_bf16(s[2 * np],     aqh, bl);
                mma_bf16(s[2 * np],     aql, bh);
                mma_bf16(s[2 * np + 1], aqh, bh + 2);
                mma_bf16(s[2 * np + 1], aqh, bl + 2);
                mma_bf16(s[2 * np + 1], aql, bh + 2);
            }
        }

        // ---- online softmax
        const bool msk = (kt >= 2 * qb);
        const int rbase = q0 + wid * 16 + (lane >> 2);
        const int kbase = kt * 64 + (lane & 3) * 2;
#pragma unroll
        for (int i = 0; i < 2; i++) {
            const int rg = rbase + i * 8;
            float mx = -1e30f;
#pragma unroll
            for (int nt = 0; nt < 8; nt++)
#pragma unroll
                for (int c = 0; c < 2; c++) {
                    float v = s[nt][i * 2 + c] * scale;
                    if (msk && (kbase + nt * 8 + c) > rg) v = -1e30f;
                    s[nt][i * 2 + c] = v;
                    mx = fmaxf(mx, v);
                }
            mx = fmaxf(mx, __shfl_xor_sync(0xffffffffu, mx, 1));
            mx = fmaxf(mx, __shfl_xor_sync(0xffffffffu, mx, 2));
            float mn = fmaxf(m_[i], mx);
            float al = __expf(m_[i] - mn);
            m_[i] = mn;
            float rs = 0.f;
#pragma unroll
            for (int nt = 0; nt < 8; nt++)
#pragma unroll
                for (int c = 0; c < 2; c++) {
                    float p = __expf(s[nt][i * 2 + c] - mn);
                    s[nt][i * 2 + c] = p;
                    rs += p;
                }
            rs += __shfl_xor_sync(0xffffffffu, rs, 1);
            rs += __shfl_xor_sync(0xffffffffu, rs, 2);
            l_[i] = l_[i] * al + rs;
#pragma unroll
            for (int nt = 0; nt < 16; nt++) { o_[nt][i * 2] *= al; o_[nt][i * 2 + 1] *= al; }
        }

        // ---- rope+split+STS K(kt+1) into other stage (loads have landed by now)
        if (pf) {
#pragma unroll
            for (int j = 0; j < 4; j++) {
                int c = ck0 + j * 4;
                float4 ra, rb;
                ra.x = kxa[j].x * kcs[j].x - kxb[j].x * ksn[j].x;  rb.x = kxb[j].x * kcs[j].x + kxa[j].x * ksn[j].x;
                ra.y = kxa[j].y * kcs[j].y - kxb[j].y * ksn[j].y;  rb.y = kxb[j].y * kcs[j].y + kxa[j].y * ksn[j].y;
                ra.z = kxa[j].z * kcs[j].z - kxb[j].z * ksn[j].z;  rb.z = kxb[j].z * kcs[j].z + kxa[j].z * ksn[j].z;
                ra.w = kxa[j].w * kcs[j].w - kxb[j].w * ksn[j].w;  rb.w = kxb[j].w * kcs[j].w + kxa[j].w * ksn[j].w;
                *(uint2*)(nst + KH_L + so_ld + c)      = make_uint2(pack_hi(ra.x, ra.y), pack_hi(ra.z, ra.w));
                *(uint2*)(nst + KL_L + so_ld + c)      = make_uint2(pack_lo(ra.x, ra.y), pack_lo(ra.z, ra.w));
                *(uint2*)(nst + KH_L + so_ld + c + 64) = make_uint2(pack_hi(rb.x, rb.y), pack_hi(rb.z, rb.w));
                *(uint2*)(nst + KL_L + so_ld + c + 64) = make_uint2(pack_lo(rb.x, rb.y), pack_lo(rb.z, rb.w));
            }
        }

        // ---- issue V(kt+1) loads (land during PV-compute)
        float4 vv[8];
        if (pf) {
            const float* vp_n = kp_n + C_;
#pragma unroll
            for (int j = 0; j < 8; j++) vv[j] = *(const float4*)(vp_n + cv0 + j * 4);
        }

        // ---- O += P V  (bf16x3; P fragments built in-register from S)
#pragma unroll
        for (int kk = 0; kk < 4; kk++) {
            uint32_t ph[4], pl[4];
            ph[0] = pack_hi(s[2 * kk][0], s[2 * kk][1]);
            ph[1] = pack_hi(s[2 * kk][2], s[2 * kk][3]);
            ph[2] = pack_hi(s[2 * kk + 1][0], s[2 * kk + 1][1]);
            ph[3] = pack_hi(s[2 * kk + 1][2], s[2 * kk + 1][3]);
            pl[0] = pack_lo(s[2 * kk][0], s[2 * kk][1]);
            pl[1] = pack_lo(s[2 * kk][2], s[2 * kk][3]);
            pl[2] = pack_lo(s[2 * kk + 1][0], s[2 * kk + 1][1]);
            pl[3] = pack_lo(s[2 * kk + 1][2], s[2 * kk + 1][3]);
#pragma unroll
            for (int np = 0; np < 8; np++) {
                uint32_t vh[4], vl[4];
                const uint32_t vr = stb + (uint32_t)((kk * 16 + (lane & 7) + ((lane >> 3) & 1) * 8) * FROWH +
                                                     np * 16 + ((lane >> 4) & 1) * 8) * 2;
                ldsm_x4_t(vh, vr + VH_L * 2);
                ldsm_x4_t(vl, vr + VL_L * 2);
                mma_bf16(o_[2 * np],     ph, vh);
                mma_bf16(o_[2 * np],     ph, vl);
                mma_bf16(o_[2 * np],     pl, vh);
                mma_bf16(o_[2 * np + 1], ph, vh + 2);
                mma_bf16(o_[2 * np + 1], ph, vl + 2);
                mma_bf16(o_[2 * np + 1], pl, vh + 2);
            }
        }

        // ---- split+STS V(kt+1)
        if (pf) {
#pragma unroll
            for (int j = 0; j < 8; j++) {
                int c = cv0 + j * 4;
                *(uint2*)(nst + VH_L + so_ld + c) = make_uint2(pack_hi(vv[j].x, vv[j].y), pack_hi(vv[j].z, vv[j].w));
                *(uint2*)(nst + VL_L + so_ld + c) = make_uint2(pack_lo(vv[j].x, vv[j].y), pack_lo(vv[j].z, vv[j].w));
            }
        }
        __syncthreads();
    }

    // ---- normalize + store to g_att [B,T,C]
    const float inv0 = 1.f / l_[0], inv1 = 1.f / l_[1];
    const int rg0 = q0 + wid * 16 + (lane >> 2);
    float* ob = g_att + (size_t)(b * T_) * C_ + h * HD_ + (lane & 3) * 2;
#pragma unroll
    for (int nt = 0; nt < 16; nt++) {
        *(float2*)(ob + (size_t)rg0 * C_ + nt * 8)       = make_float2(o_[nt][0] * inv0, o_[nt][1] * inv0);
        *(float2*)(ob + (size_t)(rg0 + 8) * C_ + nt * 8) = make_float2(o_[nt][2] * inv1, o_[nt][3] * inv1);
    }
}

// ---------------- launch ----------------
extern "C" void kernel_launch(void* const* d_in, const int* in_sizes, int n_in,
                              void* d_out, int out_size) {
    const float* x    = (const float*)d_in[0];
    const float* Wqkv = (const float*)d_in[1];
    const float* bqkv = (const float*)d_in[2];
    const float* Wo   = (const float*)d_in[3];
    const float* bo   = (const float*)d_in[4];
    float* out = (float*)d_out;

    void* qkv_p = nullptr; cudaGetSymbolAddress(&qkv_p, g_qkv);
    void* att_p = nullptr; cudaGetSymbolAddress(&att_p, g_att);

    cudaFuncSetAttribute(gemm_mma_k, cudaFuncAttributeMaxDynamicSharedMemorySize, GEMM_SMEM);
    cudaFuncSetAttribute(flash_attn_mma_k, cudaFuncAttributeMaxDynamicSharedMemorySize, FA2_SMEM);

    // 1. RoPE tables
    rope_tables_k<<<(T_ * 64 + 255) / 256, 256>>>();
    // 2. QKV projection (HMMA bf16x3)
    gemm_mma_k<<<dim3(C3_ / 128, M_ / 128), 256, GEMM_SMEM>>>(x, Wqkv, bqkv, (float*)qkv_p, C_, C3_);
    // 3. causal flash attention (HMMA, fused RoPE, pipelined) -> g_att [B,T,C]
    flash_attn_mma_k<<<dim3(T_ / 128, H_, B_), 256, FA2_SMEM>>>();
    // 4. output projection (HMMA bf16x3) -> d_out
    gemm_mma_k<<<dim3(C_ / 128, M_ / 128), 256, GEMM_SMEM>>>((const float*)att_p, Wo, bo, out, C_, C_);
}

// round 8
// speedup vs baseline: 1.1280x; 1.1280x over previous
#include <cuda_runtime.h>
#include <cuda_bf16.h>
#include <cstdint>
#include <math.h>

#define B_  2
#define T_  2048
#define C_  2048
#define H_  16
#define HD_ 128
#define C3_ 6144
#define M_  (B_*T_)

// ---------------- scratch (no allocations allowed) ----------------
__device__ float g_qkv[(size_t)B_ * T_ * C3_];   // [B,T,3C] fp32 (rope fused in attn)
__device__ float g_cos[T_ * 64];
__device__ float g_sin[T_ * 64];
// pre-split bf16 hi/lo operands
__device__ __nv_bfloat16 g_xh[(size_t)M_ * C_],  g_xl[(size_t)M_ * C_];
__device__ __nv_bfloat16 g_wqh[(size_t)C3_ * C_], g_wql[(size_t)C3_ * C_];
__device__ __nv_bfloat16 g_woh[(size_t)C_ * C_],  g_wol[(size_t)C_ * C_];
__device__ __nv_bfloat16 g_atth[(size_t)M_ * C_], g_attl[(size_t)M_ * C_];

// ---------------- RoPE tables ----------------
__global__ void rope_tables_k() {
    int idx = blockIdx.x * blockDim.x + threadIdx.x;
    if (idx >= T_ * 64) return;
    int t = idx >> 6, p = idx & 63;
    double theta = exp(-log(10000.0) * exp2((double)p) / 128.0);
    double ang = (double)(t + 1) * theta;
    g_cos[idx] = (float)cos(ang);
    g_sin[idx] = (float)sin(ang);
}

// ================= helpers =================
__device__ __forceinline__ uint32_t smem_u32(const void* p) {
    uint32_t a;
    asm("{ .reg .u64 t; cvta.to.shared.u64 t, %1; cvt.u32.u64 %0, t; }" : "=r"(a) : "l"(p));
    return a;
}
__device__ __forceinline__ void mma_bf16(float* c, const uint32_t* a, const uint32_t* b) {
    asm volatile(
        "mma.sync.aligned.m16n8k16.row.col.f32.bf16.bf16.f32 "
        "{%0,%1,%2,%3}, {%4,%5,%6,%7}, {%8,%9}, {%0,%1,%2,%3};"
        : "+f"(c[0]), "+f"(c[1]), "+f"(c[2]), "+f"(c[3])
        : "r"(a[0]), "r"(a[1]), "r"(a[2]), "r"(a[3]), "r"(b[0]), "r"(b[1]));
}
__device__ __forceinline__ void ldsm_x4(uint32_t* d, uint32_t addr) {
    asm volatile("ldmatrix.sync.aligned.m8n8.x4.shared.b16 {%0,%1,%2,%3}, [%4];"
                 : "=r"(d[0]), "=r"(d[1]), "=r"(d[2]), "=r"(d[3]) : "r"(addr));
}
__device__ __forceinline__ void ldsm_x4_t(uint32_t* d, uint32_t addr) {
    asm volatile("ldmatrix.sync.aligned.m8n8.x4.trans.shared.b16 {%0,%1,%2,%3}, [%4];"
                 : "=r"(d[0]), "=r"(d[1]), "=r"(d[2]), "=r"(d[3]) : "r"(addr));
}
__device__ __forceinline__ void ldsm_x2(uint32_t* d, uint32_t addr) {
    asm volatile("ldmatrix.sync.aligned.m8n8.x2.shared.b16 {%0,%1}, [%2];"
                 : "=r"(d[0]), "=r"(d[1]) : "r"(addr));
}
__device__ __forceinline__ uint32_t pack_hi(float x0, float x1) {
    uint32_t u0 = __float_as_uint(x0), u1 = __float_as_uint(x1);
    return (u0 >> 16) | (u1 & 0xFFFF0000u);
}
__device__ __forceinline__ uint32_t pack_lo(float x0, float x1) {
    float h0 = __uint_as_float(__float_as_uint(x0) & 0xFFFF0000u);
    float h1 = __uint_as_float(__float_as_uint(x1) & 0xFFFF0000u);
    __nv_bfloat162 v = __floats2bfloat162_rn(x0 - h0, x1 - h1);
    return *reinterpret_cast<uint32_t*>(&v);
}
#define CP_ASYNC16(dst, src) \
    asm volatile("cp.async.cg.shared.global [%0], [%1], 16;" :: "r"(dst), "l"(src))
#define CP_COMMIT() asm volatile("cp.async.commit_group;" ::: "memory")
#define CP_WAIT(n)  asm volatile("cp.async.wait_group %0;" :: "n"(n) : "memory")

// ---------------- fp32 -> bf16 hi/lo split ----------------
__global__ void split_f32_k(const float* __restrict__ src,
                            __nv_bfloat16* __restrict__ hi,
                            __nv_bfloat16* __restrict__ lo, int n4) {
    int i = blockIdx.x * blockDim.x + threadIdx.x;
    if (i >= n4) return;
    float4 v = ((const float4*)src)[i];
    ((uint2*)hi)[i] = make_uint2(pack_hi(v.x, v.y), pack_hi(v.z, v.w));
    ((uint2*)lo)[i] = make_uint2(pack_lo(v.x, v.y), pack_lo(v.z, v.w));
}

// ================= bf16x3 HMMA GEMM (NT, pre-split, cp.async): C = A*B^T + bias =======
// 128x128 CTA tile, BK=64, 8 warps (2x4), warp tile 64x32, 3-stage cp.async pipeline.
#define GROWH 72                         // halfs per smem row (128B data + 16B pad)
#define GTILE_B (128 * GROWH * 2)        // 18432 B
#define GSTAGE_B (4 * GTILE_B)           // 73728 B  (Ah, Al, Bh, Bl)
#define GEMM_SMEM (3 * GSTAGE_B)         // 221184 B

__global__ void __launch_bounds__(256)
gemm_bf16x3_k(const __nv_bfloat16* __restrict__ Ah, const __nv_bfloat16* __restrict__ Al,
              const __nv_bfloat16* __restrict__ Bh, const __nv_bfloat16* __restrict__ Bl,
              const float* __restrict__ bias, float* __restrict__ Cm,
              int K, int ldc) {
    extern __shared__ char smem[];
    const uint32_t sb = smem_u32(smem);
    const int tid = threadIdx.x;
    const int wid = tid >> 5, lid = tid & 31;
    const int m0 = blockIdx.y * 128, n0 = blockIdx.x * 128;

    const __nv_bfloat16* srcs[4] = {
        Ah + (size_t)m0 * K, Al + (size_t)m0 * K,
        Bh + (size_t)n0 * K, Bl + (size_t)n0 * K };

    // loader: per tile 128 rows x 8 16B-chunks = 1024 chunks, 4 per thread
    const int lrow = tid >> 3;           // reused: chunk row base for j-loop below
    const int lk16 = tid & 7;

    const int wm = (wid >> 2) * 64, wn = (wid & 3) * 32;
    const int a_row = (lid & 7) + ((lid >> 3) & 1) * 8;
    const int a_kb  = ((lid >> 4) & 1) * 8;
    const int b_row = lid & 7;
    const int b_kb  = ((lid >> 3) & 1) * 8;

    const int nch = K / 64;              // 32

    // stage loader
    auto load_stage = [&](int buf, int ch) {
        const uint32_t stb = sb + (uint32_t)buf * GSTAGE_B;
        const size_t ko = (size_t)ch * 64;
#pragma unroll
        for (int t = 0; t < 4; t++) {
#pragma unroll
            for (int j = 0; j < 4; j++) {
                int row = j * 32 + lrow;
                uint32_t dst = stb + (uint32_t)t * GTILE_B + (uint32_t)(row * GROWH + lk16 * 8) * 2;
                const __nv_bfloat16* src = srcs[t] + (size_t)row * K + ko + lk16 * 8;
                CP_ASYNC16(dst, src);
            }
        }
        CP_COMMIT();
    };

    float acc[4][4][4];
#pragma unroll
    for (int i = 0; i < 4; i++)
#pragma unroll
        for (int j = 0; j < 4; j++)
#pragma unroll
            for (int c = 0; c < 4; c++) acc[i][j][c] = 0.f;

    load_stage(0, 0);
    load_stage(1, 1);

    int buf = 0;
    for (int ch = 0; ch < nch; ch++) {
        if (ch < nch - 2) CP_WAIT(1); else CP_WAIT(0);
        __syncthreads();
        if (ch + 2 < nch) {
            int nb = buf + 2; if (nb >= 3) nb -= 3;
            load_stage(nb, ch + 2);
        }
        const uint32_t st = sb + (uint32_t)buf * GSTAGE_B;
#pragma unroll
        for (int ks = 0; ks < 4; ks++) {
            uint32_t ah[4][4], al[4][4], bh[4][2], bl[4][2];
#pragma unroll
            for (int mt = 0; mt < 4; mt++) {
                uint32_t ro = (uint32_t)((wm + mt * 16 + a_row) * GROWH + ks * 16 + a_kb) * 2;
                ldsm_x4(ah[mt], st + 0 * GTILE_B + ro);
                ldsm_x4(al[mt], st + 1 * GTILE_B + ro);
            }
#pragma unroll
            for (int nt = 0; nt < 4; nt++) {
                uint32_t ro = (uint32_t)((wn + nt * 8 + b_row) * GROWH + ks * 16 + b_kb) * 2;
                ldsm_x2(bh[nt], st + 2 * GTILE_B + ro);
                ldsm_x2(bl[nt], st + 3 * GTILE_B + ro);
            }
#pragma unroll
            for (int mt = 0; mt < 4; mt++)
#pragma unroll
                for (int nt = 0; nt < 4; nt++) {
                    mma_bf16(acc[mt][nt], ah[mt], bh[nt]);
                    mma_bf16(acc[mt][nt], ah[mt], bl[nt]);
                    mma_bf16(acc[mt][nt], al[mt], bh[nt]);
                }
        }
        __syncthreads();
        buf++; if (buf == 3) buf = 0;
    }

    const int cr = lid >> 2, cc = (lid & 3) * 2;
#pragma unroll
    for (int mt = 0; mt < 4; mt++) {
#pragma unroll
        for (int nt = 0; nt < 4; nt++) {
            int gr = m0 + wm + mt * 16 + cr;
            int gc = n0 + wn + nt * 8 + cc;
            float b0 = bias[gc], b1 = bias[gc + 1];
            float* p0 = Cm + (size_t)gr * ldc + gc;
            float* p1 = Cm + (size_t)(gr + 8) * ldc + gc;
            *(float2*)p0 = make_float2(acc[mt][nt][0] + b0, acc[mt][nt][1] + b1);
            *(float2*)p1 = make_float2(acc[mt][nt][2] + b0, acc[mt][nt][3] + b1);
        }
    }
}

// ================= HMMA flash attention (causal, fused RoPE, bf16x3) =================
// Round-5 structure (measured fastest); epilogue writes bf16 hi/lo for the out-proj.
#define FROWH 136
#define FQH 0
#define FQL 17408
#define FKH 34816
#define FKL 43520
#define FVH 52224
#define FVL 60928
#define FA2_SMEM (69632 * 2)

__global__ void __launch_bounds__(256, 1)
flash_attn_mma_k() {
    extern __shared__ uint16_t sh[];
    const uint32_t sb = smem_u32(sh);
    const int tid = threadIdx.x, wid = tid >> 5, lane = tid & 31;
    const int qb = (int)gridDim.x - 1 - (int)blockIdx.x;  // big work first
    const int h = blockIdx.y, b = blockIdx.z;
    const int q0 = qb * 128;
    const float scale = 0.08838834764831845f;  // 1/sqrt(128)

    // ---- Q tile load + RoPE + hi/lo split
    {
        const int r = tid >> 1, c0 = (tid & 1) * 32;
        const int t = q0 + r;
        const float* qp = g_qkv + (size_t)(b * T_ + t) * C3_ + h * HD_;
        const float* cp = g_cos + t * 64;
        const float* sp = g_sin + t * 64;
        const uint32_t so = (uint32_t)(r * FROWH);
#pragma unroll
        for (int j = 0; j < 8; j++) {
            int c = c0 + j * 4;
            float4 xa = *(const float4*)(qp + c);
            float4 xb = *(const float4*)(qp + c + 64);
            float4 cs = *(const float4*)(cp + c);
            float4 sn = *(const float4*)(sp + c);
            float4 ra, rb;
            ra.x = xa.x * cs.x - xb.x * sn.x;  rb.x = xb.x * cs.x + xa.x * sn.x;
            ra.y = xa.y * cs.y - xb.y * sn.y;  rb.y = xb.y * cs.y + xa.y * sn.y;
            ra.z = xa.z * cs.z - xb.z * sn.z;  rb.z = xb.z * cs.z + xa.z * sn.z;
            ra.w = xa.w * cs.w - xb.w * sn.w;  rb.w = xb.w * cs.w + xa.w * sn.w;
            *(uint2*)(sh + FQH + so + c)      = make_uint2(pack_hi(ra.x, ra.y), pack_hi(ra.z, ra.w));
            *(uint2*)(sh + FQL + so + c)      = make_uint2(pack_lo(ra.x, ra.y), pack_lo(ra.z, ra.w));
            *(uint2*)(sh + FQH + so + c + 64) = make_uint2(pack_hi(rb.x, rb.y), pack_hi(rb.z, rb.w));
            *(uint2*)(sh + FQL + so + c + 64) = make_uint2(pack_lo(rb.x, rb.y), pack_lo(rb.z, rb.w));
        }
    }

    float m_[2] = {-1e30f, -1e30f}, l_[2] = {0.f, 0.f};
    float o_[16][4];
#pragma unroll
    for (int nt = 0; nt < 16; nt++)
#pragma unroll
        for (int c = 0; c < 4; c++) o_[nt][c] = 0.f;

    const int ktmax = 2 * qb + 1;
    for (int kt = 0; kt <= ktmax; kt++) {
        // ---- K/V tile load + RoPE + split
        {
            const int r = tid >> 2;
            const int t = kt * 64 + r;
            const float* kp = g_qkv + (size_t)(b * T_ + t) * C3_ + C_ + h * HD_;
            const float* cp = g_cos + t * 64;
            const float* sp = g_sin + t * 64;
            const uint32_t so = (uint32_t)(r * FROWH);
            const int c0 = (tid & 3) * 16;
#pragma unroll
            for (int j = 0; j < 4; j++) {
                int c = c0 + j * 4;
                float4 xa = *(const float4*)(kp + c);
                float4 xb = *(const float4*)(kp + c + 64);
                float4 cs = *(const float4*)(cp + c);
                float4 sn = *(const float4*)(sp + c);
                float4 ra, rb;
                ra.x = xa.x * cs.x - xb.x * sn.x;  rb.x = xb.x * cs.x + xa.x * sn.x;
                ra.y = xa.y * cs.y - xb.y * sn.y;  rb.y = xb.y * cs.y + xa.y * sn.y;
                ra.z = xa.z * cs.z - xb.z * sn.z;  rb.z = xb.z * cs.z + xa.z * sn.z;
                ra.w = xa.w * cs.w - xb.w * sn.w;  rb.w = xb.w * cs.w + xa.w * sn.w;
                *(uint2*)(sh + FKH + so + c)      = make_uint2(pack_hi(ra.x, ra.y), pack_hi(ra.z, ra.w));
                *(uint2*)(sh + FKL + so + c)      = make_uint2(pack_lo(ra.x, ra.y), pack_lo(ra.z, ra.w));
                *(uint2*)(sh + FKH + so + c + 64) = make_uint2(pack_hi(rb.x, rb.y), pack_hi(rb.z, rb.w));
                *(uint2*)(sh + FKL + so + c + 64) = make_uint2(pack_lo(rb.x, rb.y), pack_lo(rb.z, rb.w));
            }
            const float* vp = kp + C_;
            const int vc0 = (tid & 3) * 32;
#pragma unroll
            for (int j = 0; j < 8; j++) {
                int c = vc0 + j * 4;
                float4 v = *(const float4*)(vp + c);
                *(uint2*)(sh + FVH + so + c) = make_uint2(pack_hi(v.x, v.y), pack_hi(v.z, v.w));
                *(uint2*)(sh + FVL + so + c) = make_uint2(pack_lo(v.x, v.y), pack_lo(v.z, v.w));
            }
        }
        __syncthreads();

        // ---- S = Q K^T (bf16x3)
        float s[8][4];
#pragma unroll
        for (int nt = 0; nt < 8; nt++)
#pragma unroll
            for (int c = 0; c < 4; c++) s[nt][c] = 0.f;

#pragma unroll
        for (int kk = 0; kk < 8; kk++) {
            uint32_t aqh[4], aql[4];
            const uint32_t ar = sb + (uint32_t)((wid * 16 + (lane & 15)) * FROWH + kk * 16 + (lane >> 4) * 8) * 2;
            ldsm_x4(aqh, ar + FQH * 2);
            ldsm_x4(aql, ar + FQL * 2);
#pragma unroll
            for (int np = 0; np < 4; np++) {
                uint32_t bh[4], bl[4];
                const uint32_t br = sb + (uint32_t)((np * 16 + (lane & 7) + ((lane >> 4) & 1) * 8) * FROWH +
                                                    kk * 16 + ((lane >> 3) & 1) * 8) * 2;
                ldsm_x4(bh, br + FKH * 2);
                ldsm_x4(bl, br + FKL * 2);
                mma_bf16(s[2 * np],     aqh, bh);
                mma_bf16(s[2 * np],     aqh, bl);
                mma_bf16(s[2 * np],     aql, bh);
                mma_bf16(s[2 * np + 1], aqh, bh + 2);
                mma_bf16(s[2 * np + 1], aqh, bl + 2);
                mma_bf16(s[2 * np + 1], aql, bh + 2);
            }
        }

        // ---- online softmax
        const bool msk = (kt >= 2 * qb);
        const int rbase = q0 + wid * 16 + (lane >> 2);
        const int kbase = kt * 64 + (lane & 3) * 2;
#pragma unroll
        for (int i = 0; i < 2; i++) {
            const int rg = rbase + i * 8;
            float mx = -1e30f;
#pragma unroll
            for (int nt = 0; nt < 8; nt++)
#pragma unroll
                for (int c = 0; c < 2; c++) {
                    float v = s[nt][i * 2 + c] * scale;
                    if (msk && (kbase + nt * 8 + c) > rg) v = -1e30f;
                    s[nt][i * 2 + c] = v;
                    mx = fmaxf(mx, v);
                }
            mx = fmaxf(mx, __shfl_xor_sync(0xffffffffu, mx, 1));
            mx = fmaxf(mx, __shfl_xor_sync(0xffffffffu, mx, 2));
            float mn = fmaxf(m_[i], mx);
            float al = __expf(m_[i] - mn);
            m_[i] = mn;
            float rs = 0.f;
#pragma unroll
            for (int nt = 0; nt < 8; nt++)
#pragma unroll
                for (int c = 0; c < 2; c++) {
                    float p = __expf(s[nt][i * 2 + c] - mn);
                    s[nt][i * 2 + c] = p;
                    rs += p;
                }
            rs += __shfl_xor_sync(0xffffffffu, rs, 1);
            rs += __shfl_xor_sync(0xffffffffu, rs, 2);
            l_[i] = l_[i] * al + rs;
#pragma unroll
            for (int nt = 0; nt < 16; nt++) { o_[nt][i * 2] *= al; o_[nt][i * 2 + 1] *= al; }
        }

        // ---- O += P V (bf16x3)
#pragma unroll
        for (int kk = 0; kk < 4; kk++) {
            uint32_t ph[4], pl[4];
            ph[0] = pack_hi(s[2 * kk][0], s[2 * kk][1]);
            ph[1] = pack_hi(s[2 * kk][2], s[2 * kk][3]);
            ph[2] = pack_hi(s[2 * kk + 1][0], s[2 * kk + 1][1]);
            ph[3] = pack_hi(s[2 * kk + 1][2], s[2 * kk + 1][3]);
            pl[0] = pack_lo(s[2 * kk][0], s[2 * kk][1]);
            pl[1] = pack_lo(s[2 * kk][2], s[2 * kk][3]);
            pl[2] = pack_lo(s[2 * kk + 1][0], s[2 * kk + 1][1]);
            pl[3] = pack_lo(s[2 * kk + 1][2], s[2 * kk + 1][3]);
#pragma unroll
            for (int np = 0; np < 8; np++) {
                uint32_t vh[4], vl[4];
                const uint32_t vr = sb + (uint32_t)((kk * 16 + (lane & 7) + ((lane >> 3) & 1) * 8) * FROWH +
                                                    np * 16 + ((lane >> 4) & 1) * 8) * 2;
                ldsm_x4_t(vh, vr + FVH * 2);
                ldsm_x4_t(vl, vr + FVL * 2);
                mma_bf16(o_[2 * np],     ph, vh);
                mma_bf16(o_[2 * np],     ph, vl);
                mma_bf16(o_[2 * np],     pl, vh);
                mma_bf16(o_[2 * np + 1], ph, vh + 2);
                mma_bf16(o_[2 * np + 1], ph, vl + 2);
                mma_bf16(o_[2 * np + 1], pl, vh + 2);
            }
        }
        __syncthreads();
    }

    // ---- normalize + store bf16 hi/lo to g_atth/g_attl [B,T,C]
    const float inv0 = 1.f / l_[0], inv1 = 1.f / l_[1];
    const int rg0 = b * T_ + q0 + wid * 16 + (lane >> 2);
    const size_t colb = (size_t)h * HD_ + (lane & 3) * 2;
#pragma unroll
    for (int nt = 0; nt < 16; nt++) {
        float a0 = o_[nt][0] * inv0, a1 = o_[nt][1] * inv0;
        float b0 = o_[nt][2] * inv1, b1 = o_[nt][3] * inv1;
        size_t off0 = (size_t)rg0 * C_ + colb + nt * 8;
        size_t off1 = (size_t)(rg0 + 8) * C_ + colb + nt * 8;
        *(uint32_t*)&g_atth[off0] = pack_hi(a0, a1);
        *(uint32_t*)&g_attl[off0] = pack_lo(a0, a1);
        *(uint32_t*)&g_atth[off1] = pack_hi(b0, b1);
        *(uint32_t*)&g_attl[off1] = pack_lo(b0, b1);
    }
}

// ---------------- launch ----------------
extern "C" void kernel_launch(void* const* d_in, const int* in_sizes, int n_in,
                              void* d_out, int out_size) {
    const float* x    = (const float*)d_in[0];
    const float* Wqkv = (const float*)d_in[1];
    const float* bqkv = (const float*)d_in[2];
    const float* Wo   = (const float*)d_in[3];
    const float* bo   = (const float*)d_in[4];
    float* out = (float*)d_out;

    void* qkv_p = nullptr; cudaGetSymbolAddress(&qkv_p, g_qkv);
    void *xh, *xl, *wqh, *wql, *woh, *wol, *ath, *atl;
    cudaGetSymbolAddress(&xh, g_xh);   cudaGetSymbolAddress(&xl, g_xl);
    cudaGetSymbolAddress(&wqh, g_wqh); cudaGetSymbolAddress(&wql, g_wql);
    cudaGetSymbolAddress(&woh, g_woh); cudaGetSymbolAddress(&wol, g_wol);
    cudaGetSymbolAddress(&ath, g_atth); cudaGetSymbolAddress(&atl, g_attl);

    cudaFuncSetAttribute(gemm_bf16x3_k, cudaFuncAttributeMaxDynamicSharedMemorySize, GEMM_SMEM);
    cudaFuncSetAttribute(flash_attn_mma_k, cudaFuncAttributeMaxDynamicSharedMemorySize, FA2_SMEM);

    // 1. RoPE tables + operand pre-splits
    rope_tables_k<<<(T_ * 64 + 255) / 256, 256>>>();
    split_f32_k<<<(M_ * C_ / 4 + 255) / 256, 256>>>(x, (__nv_bfloat16*)xh, (__nv_bfloat16*)xl, M_ * C_ / 4);
    split_f32_k<<<(C3_ * C_ / 4 + 255) / 256, 256>>>(Wqkv, (__nv_bfloat16*)wqh, (__nv_bfloat16*)wql, C3_ * C_ / 4);
    split_f32_k<<<(C_ * C_ / 4 + 255) / 256, 256>>>(Wo, (__nv_bfloat16*)woh, (__nv_bfloat16*)wol, C_ * C_ / 4);
    // 2. QKV projection (cp.async bf16x3)
    gemm_bf16x3_k<<<dim3(C3_ / 128, M_ / 128), 256, GEMM_SMEM>>>(
        (const __nv_bfloat16*)xh, (const __nv_bfloat16*)xl,
        (const __nv_bfloat16*)wqh, (const __nv_bfloat16*)wql, bqkv, (float*)qkv_p, C_, C3_);
    // 3. causal flash attention (HMMA, fused RoPE) -> g_atth/g_attl
    flash_attn_mma_k<<<dim3(T_ / 128, H_, B_), 256, FA2_SMEM>>>();
    // 4. output projection (cp.async bf16x3) -> d_out
    gemm_bf16x3_k<<<dim3(C_ / 128, M_ / 128), 256, GEMM_SMEM>>>(
        (const __nv_bfloat16*)ath, (const __nv_bfloat16*)atl,
        (const __nv_bfloat16*)woh, (const __nv_bfloat16*)wol, bo, out, C_, C_);
}

// round 9
// speedup vs baseline: 1.1675x; 1.0351x over previous
#include <cuda_runtime.h>
#include <cuda_bf16.h>
#include <cstdint>
#include <math.h>

#define B_  2
#define T_  2048
#define C_  2048
#define H_  16
#define HD_ 128
#define C3_ 6144
#define M_  (B_*T_)

// ---------------- scratch (no allocations allowed) ----------------
__device__ float g_qkv[(size_t)B_ * T_ * C3_];   // [B,T,3C] fp32 (rope fused in attn)
__device__ float g_cos[T_ * 64];
__device__ float g_sin[T_ * 64];
// pre-split bf16 hi/lo operands
__device__ __nv_bfloat16 g_xh[(size_t)M_ * C_],  g_xl[(size_t)M_ * C_];
__device__ __nv_bfloat16 g_wqh[(size_t)C3_ * C_], g_wql[(size_t)C3_ * C_];
__device__ __nv_bfloat16 g_woh[(size_t)C_ * C_],  g_wol[(size_t)C_ * C_];
__device__ __nv_bfloat16 g_atth[(size_t)M_ * C_], g_attl[(size_t)M_ * C_];

// ---------------- RoPE tables ----------------
__global__ void rope_tables_k() {
    int idx = blockIdx.x * blockDim.x + threadIdx.x;
    if (idx >= T_ * 64) return;
    int t = idx >> 6, p = idx & 63;
    double theta = exp(-log(10000.0) * exp2((double)p) / 128.0);
    double ang = (double)(t + 1) * theta;
    g_cos[idx] = (float)cos(ang);
    g_sin[idx] = (float)sin(ang);
}

// ================= helpers =================
__device__ __forceinline__ uint32_t smem_u32(const void* p) {
    uint32_t a;
    asm("{ .reg .u64 t; cvta.to.shared.u64 t, %1; cvt.u32.u64 %0, t; }" : "=r"(a) : "l"(p));
    return a;
}
__device__ __forceinline__ void mma_bf16(float* c, const uint32_t* a, const uint32_t* b) {
    asm volatile(
        "mma.sync.aligned.m16n8k16.row.col.f32.bf16.bf16.f32 "
        "{%0,%1,%2,%3}, {%4,%5,%6,%7}, {%8,%9}, {%0,%1,%2,%3};"
        : "+f"(c[0]), "+f"(c[1]), "+f"(c[2]), "+f"(c[3])
        : "r"(a[0]), "r"(a[1]), "r"(a[2]), "r"(a[3]), "r"(b[0]), "r"(b[1]));
}
__device__ __forceinline__ void ldsm_x4(uint32_t* d, uint32_t addr) {
    asm volatile("ldmatrix.sync.aligned.m8n8.x4.shared.b16 {%0,%1,%2,%3}, [%4];"
                 : "=r"(d[0]), "=r"(d[1]), "=r"(d[2]), "=r"(d[3]) : "r"(addr));
}
__device__ __forceinline__ void ldsm_x4_t(uint32_t* d, uint32_t addr) {
    asm volatile("ldmatrix.sync.aligned.m8n8.x4.trans.shared.b16 {%0,%1,%2,%3}, [%4];"
                 : "=r"(d[0]), "=r"(d[1]), "=r"(d[2]), "=r"(d[3]) : "r"(addr));
}
__device__ __forceinline__ uint32_t pack_hi(float x0, float x1) {
    uint32_t u0 = __float_as_uint(x0), u1 = __float_as_uint(x1);
    return (u0 >> 16) | (u1 & 0xFFFF0000u);
}
__device__ __forceinline__ uint32_t pack_lo(float x0, float x1) {
    float h0 = __uint_as_float(__float_as_uint(x0) & 0xFFFF0000u);
    float h1 = __uint_as_float(__float_as_uint(x1) & 0xFFFF0000u);
    __nv_bfloat162 v = __floats2bfloat162_rn(x0 - h0, x1 - h1);
    return *reinterpret_cast<uint32_t*>(&v);
}
#define CP_ASYNC16(dst, src) \
    asm volatile("cp.async.cg.shared.global [%0], [%1], 16;" :: "r"(dst), "l"(src))
#define CP_COMMIT() asm volatile("cp.async.commit_group;" ::: "memory")
#define CP_WAIT(n)  asm volatile("cp.async.wait_group %0;" :: "n"(n) : "memory")

// ---------------- fp32 -> bf16 hi/lo split ----------------
__global__ void split_f32_k(const float* __restrict__ src,
                            __nv_bfloat16* __restrict__ hi,
                            __nv_bfloat16* __restrict__ lo, int n4) {
    int i = blockIdx.x * blockDim.x + threadIdx.x;
    if (i >= n4) return;
    float4 v = ((const float4*)src)[i];
    ((uint2*)hi)[i] = make_uint2(pack_hi(v.x, v.y), pack_hi(v.z, v.w));
    ((uint2*)lo)[i] = make_uint2(pack_lo(v.x, v.y), pack_lo(v.z, v.w));
}

// ===== bf16x3 HMMA GEMM (NT, pre-split, cp.async): C = A[M,K]*B[N,K]^T + bias =====
// BM=256, BN=128, BK=64, 8 warps in 4x2, warp tile 64x64, 2-stage cp.async pipeline.
#define GROWH 72                          // halfs per smem row (128B data + 16B pad)
#define ATILE_B (256 * GROWH * 2)         // 36864 B
#define BTILE_B (128 * GROWH * 2)         // 18432 B
#define GB_OFF  (2 * ATILE_B)             // 73728
#define GSTAGE_B (2 * ATILE_B + 2 * BTILE_B)  // 110592 B
#define GEMM_SMEM (2 * GSTAGE_B)          // 221184 B

__global__ void __launch_bounds__(256, 1)
gemm_bf16x3_k(const __nv_bfloat16* __restrict__ Ah, const __nv_bfloat16* __restrict__ Al,
              const __nv_bfloat16* __restrict__ Bh, const __nv_bfloat16* __restrict__ Bl,
              const float* __restrict__ bias, float* __restrict__ Cm,
              int K, int ldc) {
    extern __shared__ char smem[];
    const uint32_t sb = smem_u32(smem);
    const int tid = threadIdx.x;
    const int wid = tid >> 5, lid = tid & 31;
    const int m0 = blockIdx.y * 256, n0 = blockIdx.x * 128;

    const __nv_bfloat16* a_srcs[2] = { Ah + (size_t)m0 * K, Al + (size_t)m0 * K };
    const __nv_bfloat16* b_srcs[2] = { Bh + (size_t)n0 * K, Bl + (size_t)n0 * K };

    const int lrow = tid >> 3;            // 0..31
    const int lk16 = tid & 7;             // 16B chunk within 128B row

    const int wm = (wid >> 1) * 64, wn = (wid & 1) * 64;
    // ldmatrix lane mappings
    const int a_row = (lid & 7) + ((lid >> 3) & 1) * 8;
    const int a_kb  = ((lid >> 4) & 1) * 8;
    const int b_row = (lid & 7) + ((lid >> 4) & 1) * 8;   // x4 pair-load for B
    const int b_kb  = ((lid >> 3) & 1) * 8;

    const int nch = K / 64;

    auto load_stage = [&](int buf, int ch) {
        const uint32_t stb = sb + (uint32_t)buf * GSTAGE_B;
        const size_t ko = (size_t)ch * 64;
#pragma unroll
        for (int t = 0; t < 2; t++) {
#pragma unroll
            for (int j = 0; j < 8; j++) {                 // A: 256 rows
                int row = j * 32 + lrow;
                uint32_t dst = stb + (uint32_t)t * ATILE_B + (uint32_t)(row * GROWH + lk16 * 8) * 2;
                CP_ASYNC16(dst, a_srcs[t] + (size_t)row * K + ko + lk16 * 8);
            }
#pragma unroll
            for (int j = 0; j < 4; j++) {                 // B: 128 rows
                int row = j * 32 + lrow;
                uint32_t dst = stb + GB_OFF + (uint32_t)t * BTILE_B + (uint32_t)(row * GROWH + lk16 * 8) * 2;
                CP_ASYNC16(dst, b_srcs[t] + (size_t)row * K + ko + lk16 * 8);
            }
        }
        CP_COMMIT();
    };

    float acc[4][8][4];
#pragma unroll
    for (int i = 0; i < 4; i++)
#pragma unroll
        for (int j = 0; j < 8; j++)
#pragma unroll
            for (int c = 0; c < 4; c++) acc[i][j][c] = 0.f;

    load_stage(0, 0);
    if (nch > 1) load_stage(1, 1);

    for (int ch = 0; ch < nch; ch++) {
        if (ch + 1 < nch) CP_WAIT(1); else CP_WAIT(0);
        __syncthreads();
        const uint32_t st = sb + (uint32_t)(ch & 1) * GSTAGE_B;
#pragma unroll
        for (int ks = 0; ks < 4; ks++) {
            uint32_t ah[4][4], al[4][4];
#pragma unroll
            for (int mt = 0; mt < 4; mt++) {
                uint32_t ro = (uint32_t)((wm + mt * 16 + a_row) * GROWH + ks * 16 + a_kb) * 2;
                ldsm_x4(ah[mt], st + 0 * ATILE_B + ro);
                ldsm_x4(al[mt], st + 1 * ATILE_B + ro);
            }
#pragma unroll
            for (int half = 0; half < 2; half++) {
                uint32_t bh[2][4], bl[2][4];
#pragma unroll
                for (int p = 0; p < 2; p++) {
                    int np = half * 2 + p;
                    uint32_t ro = (uint32_t)((wn + np * 16 + b_row) * GROWH + ks * 16 + b_kb) * 2;
                    ldsm_x4(bh[p], st + GB_OFF + 0 * BTILE_B + ro);
                    ldsm_x4(bl[p], st + GB_OFF + 1 * BTILE_B + ro);
                }
#pragma unroll
                for (int mt = 0; mt < 4; mt++)
#pragma unroll
                    for (int p = 0; p < 2; p++) {
                        int nt = half * 4 + p * 2;
                        mma_bf16(acc[mt][nt],     ah[mt], bh[p]);
                        mma_bf16(acc[mt][nt],     ah[mt], bl[p]);
                        mma_bf16(acc[mt][nt],     al[mt], bh[p]);
                        mma_bf16(acc[mt][nt + 1], ah[mt], bh[p] + 2);
                        mma_bf16(acc[mt][nt + 1], ah[mt], bl[p] + 2);
                        mma_bf16(acc[mt][nt + 1], al[mt], bh[p] + 2);
                    }
            }
        }
        __syncthreads();
        if (ch + 2 < nch) load_stage(ch & 1, ch + 2);
    }

    const int cr = lid >> 2, cc = (lid & 3) * 2;
#pragma unroll
    for (int mt = 0; mt < 4; mt++) {
#pragma unroll
        for (int nt = 0; nt < 8; nt++) {
            int gr = m0 + wm + mt * 16 + cr;
            int gc = n0 + wn + nt * 8 + cc;
            float b0 = bias[gc], b1 = bias[gc + 1];
            float* p0 = Cm + (size_t)gr * ldc + gc;
            float* p1 = Cm + (size_t)(gr + 8) * ldc + gc;
            *(float2*)p0 = make_float2(acc[mt][nt][0] + b0, acc[mt][nt][1] + b1);
            *(float2*)p1 = make_float2(acc[mt][nt][2] + b0, acc[mt][nt][3] + b1);
        }
    }
}

// ================= HMMA flash attention (causal, fused RoPE, bf16x3) =================
#define FROWH 136
#define FQH 0
#define FQL 17408
#define FKH 34816
#define FKL 43520
#define FVH 52224
#define FVL 60928
#define FA2_SMEM (69632 * 2)

__global__ void __launch_bounds__(256, 1)
flash_attn_mma_k() {
    extern __shared__ uint16_t sh[];
    const uint32_t sb = smem_u32(sh);
    const int tid = threadIdx.x, wid = tid >> 5, lane = tid & 31;
    const int qb = (int)gridDim.x - 1 - (int)blockIdx.x;  // big work first
    const int h = blockIdx.y, b = blockIdx.z;
    const int q0 = qb * 128;
    const float scale = 0.08838834764831845f;  // 1/sqrt(128)

    // ---- Q tile load + RoPE + hi/lo split
    {
        const int r = tid >> 1, c0 = (tid & 1) * 32;
        const int t = q0 + r;
        const float* qp = g_qkv + (size_t)(b * T_ + t) * C3_ + h * HD_;
        const float* cp = g_cos + t * 64;
        const float* sp = g_sin + t * 64;
        const uint32_t so = (uint32_t)(r * FROWH);
#pragma unroll
        for (int j = 0; j < 8; j++) {
            int c = c0 + j * 4;
            float4 xa = *(const float4*)(qp + c);
            float4 xb = *(const float4*)(qp + c + 64);
            float4 cs = *(const float4*)(cp + c);
            float4 sn = *(const float4*)(sp + c);
            float4 ra, rb;
            ra.x = xa.x * cs.x - xb.x * sn.x;  rb.x = xb.x * cs.x + xa.x * sn.x;
            ra.y = xa.y * cs.y - xb.y * sn.y;  rb.y = xb.y * cs.y + xa.y * sn.y;
            ra.z = xa.z * cs.z - xb.z * sn.z;  rb.z = xb.z * cs.z + xa.z * sn.z;
            ra.w = xa.w * cs.w - xb.w * sn.w;  rb.w = xb.w * cs.w + xa.w * sn.w;
            *(uint2*)(sh + FQH + so + c)      = make_uint2(pack_hi(ra.x, ra.y), pack_hi(ra.z, ra.w));
            *(uint2*)(sh + FQL + so + c)      = make_uint2(pack_lo(ra.x, ra.y), pack_lo(ra.z, ra.w));
            *(uint2*)(sh + FQH + so + c + 64) = make_uint2(pack_hi(rb.x, rb.y), pack_hi(rb.z, rb.w));
            *(uint2*)(sh + FQL + so + c + 64) = make_uint2(pack_lo(rb.x, rb.y), pack_lo(rb.z, rb.w));
        }
    }

    float m_[2] = {-1e30f, -1e30f}, l_[2] = {0.f, 0.f};
    float o_[16][4];
#pragma unroll
    for (int nt = 0; nt < 16; nt++)
#pragma unroll
        for (int c = 0; c < 4; c++) o_[nt][c] = 0.f;

    const int ktmax = 2 * qb + 1;
    for (int kt = 0; kt <= ktmax; kt++) {
        // ---- K/V tile load + RoPE + split
        {
            const int r = tid >> 2;
            const int t = kt * 64 + r;
            const float* kp = g_qkv + (size_t)(b * T_ + t) * C3_ + C_ + h * HD_;
            const float* cp = g_cos + t * 64;
            const float* sp = g_sin + t * 64;
            const uint32_t so = (uint32_t)(r * FROWH);
            const int c0 = (tid & 3) * 16;
#pragma unroll
            for (int j = 0; j < 4; j++) {
                int c = c0 + j * 4;
                float4 xa = *(const float4*)(kp + c);
                float4 xb = *(const float4*)(kp + c + 64);
                float4 cs = *(const float4*)(cp + c);
                float4 sn = *(const float4*)(sp + c);
                float4 ra, rb;
                ra.x = xa.x * cs.x - xb.x * sn.x;  rb.x = xb.x * cs.x + xa.x * sn.x;
                ra.y = xa.y * cs.y - xb.y * sn.y;  rb.y = xb.y * cs.y + xa.y * sn.y;
                ra.z = xa.z * cs.z - xb.z * sn.z;  rb.z = xb.z * cs.z + xa.z * sn.z;
                ra.w = xa.w * cs.w - xb.w * sn.w;  rb.w = xb.w * cs.w + xa.w * sn.w;
                *(uint2*)(sh + FKH + so + c)      = make_uint2(pack_hi(ra.x, ra.y), pack_hi(ra.z, ra.w));
                *(uint2*)(sh + FKL + so + c)      = make_uint2(pack_lo(ra.x, ra.y), pack_lo(ra.z, ra.w));
                *(uint2*)(sh + FKH + so + c + 64) = make_uint2(pack_hi(rb.x, rb.y), pack_hi(rb.z, rb.w));
                *(uint2*)(sh + FKL + so + c + 64) = make_uint2(pack_lo(rb.x, rb.y), pack_lo(rb.z, rb.w));
            }
            const float* vp = kp + C_;
            const int vc0 = (tid & 3) * 32;
#pragma unroll
            for (int j = 0; j < 8; j++) {
                int c = vc0 + j * 4;
                float4 v = *(const float4*)(vp + c);
                *(uint2*)(sh + FVH + so + c) = make_uint2(pack_hi(v.x, v.y), pack_hi(v.z, v.w));
                *(uint2*)(sh + FVL + so + c) = make_uint2(pack_lo(v.x, v.y), pack_lo(v.z, v.w));
            }
        }
        __syncthreads();

        // ---- S = Q K^T (bf16x3)
        float s[8][4];
#pragma unroll
        for (int nt = 0; nt < 8; nt++)
#pragma unroll
            for (int c = 0; c < 4; c++) s[nt][c] = 0.f;

#pragma unroll
        for (int kk = 0; kk < 8; kk++) {
            uint32_t aqh[4], aql[4];
            const uint32_t ar = sb + (uint32_t)((wid * 16 + (lane & 15)) * FROWH + kk * 16 + (lane >> 4) * 8) * 2;
            ldsm_x4(aqh, ar + FQH * 2);
            ldsm_x4(aql, ar + FQL * 2);
#pragma unroll
            for (int np = 0; np < 4; np++) {
                uint32_t bh[4], bl[4];
                const uint32_t br = sb + (uint32_t)((np * 16 + (lane & 7) + ((lane >> 4) & 1) * 8) * FROWH +
                                                    kk * 16 + ((lane >> 3) & 1) * 8) * 2;
                ldsm_x4(bh, br + FKH * 2);
                ldsm_x4(bl, br + FKL * 2);
                mma_bf16(s[2 * np],     aqh, bh);
                mma_bf16(s[2 * np],     aqh, bl);
                mma_bf16(s[2 * np],     aql, bh);
                mma_bf16(s[2 * np + 1], aqh, bh + 2);
                mma_bf16(s[2 * np + 1], aqh, bl + 2);
                mma_bf16(s[2 * np + 1], aql, bh + 2);
            }
        }

        // ---- online softmax
        const bool msk = (kt >= 2 * qb);
        const int rbase = q0 + wid * 16 + (lane >> 2);
        const int kbase = kt * 64 + (lane & 3) * 2;
#pragma unroll
        for (int i = 0; i < 2; i++) {
            const int rg = rbase + i * 8;
            float mx = -1e30f;
#pragma unroll
            for (int nt = 0; nt < 8; nt++)
#pragma unroll
                for (int c = 0; c < 2; c++) {
                    float v = s[nt][i * 2 + c] * scale;
                    if (msk && (kbase + nt * 8 + c) > rg) v = -1e30f;
                    s[nt][i * 2 + c] = v;
                    mx = fmaxf(mx, v);
                }
            mx = fmaxf(mx, __shfl_xor_sync(0xffffffffu, mx, 1));
            mx = fmaxf(mx, __shfl_xor_sync(0xffffffffu, mx, 2));
            float mn = fmaxf(m_[i], mx);
            float al = __expf(m_[i] - mn);
            m_[i] = mn;
            float rs = 0.f;
#pragma unroll
            for (int nt = 0; nt < 8; nt++)
#pragma unroll
                for (int c = 0; c < 2; c++) {
                    float p = __expf(s[nt][i * 2 + c] - mn);
                    s[nt][i * 2 + c] = p;
                    rs += p;
                }
            rs += __shfl_xor_sync(0xffffffffu, rs, 1);
            rs += __shfl_xor_sync(0xffffffffu, rs, 2);
            l_[i] = l_[i] * al + rs;
#pragma unroll
            for (int nt = 0; nt < 16; nt++) { o_[nt][i * 2] *= al; o_[nt][i * 2 + 1] *= al; }
        }

        // ---- O += P V (bf16x3)
#pragma unroll
        for (int kk = 0; kk < 4; kk++) {
            uint32_t ph[4], pl[4];
            ph[0] = pack_hi(s[2 * kk][0], s[2 * kk][1]);
            ph[1] = pack_hi(s[2 * kk][2], s[2 * kk][3]);
            ph[2] = pack_hi(s[2 * kk + 1][0], s[2 * kk + 1][1]);
            ph[3] = pack_hi(s[2 * kk + 1][2], s[2 * kk + 1][3]);
            pl[0] = pack_lo(s[2 * kk][0], s[2 * kk][1]);
            pl[1] = pack_lo(s[2 * kk][2], s[2 * kk][3]);
            pl[2] = pack_lo(s[2 * kk + 1][0], s[2 * kk + 1][1]);
            pl[3] = pack_lo(s[2 * kk + 1][2], s[2 * kk + 1][3]);
#pragma unroll
            for (int np = 0; np < 8; np++) {
                uint32_t vh[4], vl[4];
                const uint32_t vr = sb + (uint32_t)((kk * 16 + (lane & 7) + ((lane >> 3) & 1) * 8) * FROWH +
                                                    np * 16 + ((lane >> 4) & 1) * 8) * 2;
                ldsm_x4_t(vh, vr + FVH * 2);
                ldsm_x4_t(vl, vr + FVL * 2);
                mma_bf16(o_[2 * np],     ph, vh);
                mma_bf16(o_[2 * np],     ph, vl);
                mma_bf16(o_[2 * np],     pl, vh);
                mma_bf16(o_[2 * np + 1], ph, vh + 2);
                mma_bf16(o_[2 * np + 1], ph, vl + 2);
                mma_bf16(o_[2 * np + 1], pl, vh + 2);
            }
        }
        __syncthreads();
    }

    // ---- normalize + store bf16 hi/lo to g_atth/g_attl [B,T,C]
    const float inv0 = 1.f / l_[0], inv1 = 1.f / l_[1];
    const int rg0 = b * T_ + q0 + wid * 16 + (lane >> 2);
    const size_t colb = (size_t)h * HD_ + (lane & 3) * 2;
#pragma unroll
    for (int nt = 0; nt < 16; nt++) {
        float a0 = o_[nt][0] * inv0, a1 = o_[nt][1] * inv0;
        float b0 = o_[nt][2] * inv1, b1 = o_[nt][3] * inv1;
        size_t off0 = (size_t)rg0 * C_ + colb + nt * 8;
        size_t off1 = (size_t)(rg0 + 8) * C_ + colb + nt * 8;
        *(uint32_t*)&g_atth[off0] = pack_hi(a0, a1);
        *(uint32_t*)&g_attl[off0] = pack_lo(a0, a1);
        *(uint32_t*)&g_atth[off1] = pack_hi(b0, b1);
        *(uint32_t*)&g_attl[off1] = pack_lo(b0, b1);
    }
}

// ---------------- launch ----------------
extern "C" void kernel_launch(void* const* d_in, const int* in_sizes, int n_in,
                              void* d_out, int out_size) {
    const float* x    = (const float*)d_in[0];
    const float* Wqkv = (const float*)d_in[1];
    const float* bqkv = (const float*)d_in[2];
    const float* Wo   = (const float*)d_in[3];
    const float* bo   = (const float*)d_in[4];
    float* out = (float*)d_out;

    void* qkv_p = nullptr; cudaGetSymbolAddress(&qkv_p, g_qkv);
    void *xh, *xl, *wqh, *wql, *woh, *wol, *ath, *atl;
    cudaGetSymbolAddress(&xh, g_xh);   cudaGetSymbolAddress(&xl, g_xl);
    cudaGetSymbolAddress(&wqh, g_wqh); cudaGetSymbolAddress(&wql, g_wql);
    cudaGetSymbolAddress(&woh, g_woh); cudaGetSymbolAddress(&wol, g_wol);
    cudaGetSymbolAddress(&ath, g_atth); cudaGetSymbolAddress(&atl, g_attl);

    cudaFuncSetAttribute(gemm_bf16x3_k, cudaFuncAttributeMaxDynamicSharedMemorySize, GEMM_SMEM);
    cudaFuncSetAttribute(flash_attn_mma_k, cudaFuncAttributeMaxDynamicSharedMemorySize, FA2_SMEM);

    // 1. RoPE tables + operand pre-splits
    rope_tables_k<<<(T_ * 64 + 255) / 256, 256>>>();
    split_f32_k<<<(M_ * C_ / 4 + 255) / 256, 256>>>(x, (__nv_bfloat16*)xh, (__nv_bfloat16*)xl, M_ * C_ / 4);
    split_f32_k<<<(C3_ * C_ / 4 + 255) / 256, 256>>>(Wqkv, (__nv_bfloat16*)wqh, (__nv_bfloat16*)wql, C3_ * C_ / 4);
    split_f32_k<<<(C_ * C_ / 4 + 255) / 256, 256>>>(Wo, (__nv_bfloat16*)woh, (__nv_bfloat16*)wol, C_ * C_ / 4);
    // 2. QKV projection (cp.async bf16x3, 256x128 tiles)
    gemm_bf16x3_k<<<dim3(C3_ / 128, M_ / 256), 256, GEMM_SMEM>>>(
        (const __nv_bfloat16*)xh, (const __nv_bfloat16*)xl,
        (const __nv_bfloat16*)wqh, (const __nv_bfloat16*)wql, bqkv, (float*)qkv_p, C_, C3_);
    // 3. causal flash attention (HMMA, fused RoPE) -> g_atth/g_attl
    flash_attn_mma_k<<<dim3(T_ / 128, H_, B_), 256, FA2_SMEM>>>();
    // 4. output projection (cp.async bf16x3, 256x128 tiles) -> d_out
    gemm_bf16x3_k<<<dim3(C_ / 128, M_ / 256), 256, GEMM_SMEM>>>(
        (const __nv_bfloat16*)ath, (const __nv_bfloat16*)atl,
        (const __nv_bfloat16*)woh, (const __nv_bfloat16*)wol, bo, out, C_, C_);
}